// round 6
// baseline (speedup 1.0000x reference)
#include <cuda_runtime.h>

// Local 5x5 variance, reflect padding. float32 [16,3,1024,1024] -> same.
//
// Fully streaming, no shared memory, no barriers:
//   CTA = 256 threads as 16(x) x 16(y); thread owns 4 cols x 16 rows.
//   Per input row: 3x LDG.128 (12 floats), horizontal 5-sums of x and x^2
//   computed incrementally in registers, 5-row register ring for vertical
//   5-sum, one float4 STG per output row. L1/L2 absorb halo overlap.

#define IMG 1024
#define NPLANES 48
#define ROWS_PER_THREAD 16
#define THREADS 256

__device__ __forceinline__ int reflect_idx(int i, int n) {
    if (i < 0) i = -i;
    if (i >= n) i = 2 * (n - 1) - i;
    return i;
}

// Horizontal 5-sums of x and x^2 for 4 consecutive output columns from the
// 12-float window (a|b|c); outputs use floats 2..9 of the window.
__device__ __forceinline__ void rowsum(float4 a, float4 b, float4 c,
                                       float* __restrict__ hh,
                                       float* __restrict__ hh2) {
    float x0 = a.z, x1 = a.w, x2 = b.x, x3 = b.y;
    float x4 = b.z, x5 = b.w, x6 = c.x, x7 = c.y;

    float h0 = x0 + x1 + x2 + x3 + x4;
    hh[0] = h0;
    hh[1] = h0    - x0 + x5;
    hh[2] = hh[1] - x1 + x6;
    hh[3] = hh[2] - x2 + x7;

    float q0 = x0 * x0, q1 = x1 * x1, q2 = x2 * x2, q3 = x3 * x3;
    float q4 = x4 * x4, q5 = x5 * x5, q6 = x6 * x6, q7 = x7 * x7;
    float g0 = q0 + q1 + q2 + q3 + q4;
    hh2[0] = g0;
    hh2[1] = g0     - q0 + q5;
    hh2[2] = hh2[1] - q1 + q6;
    hh2[3] = hh2[2] - q2 + q7;
}

__device__ __forceinline__ void load_row(const float* __restrict__ rowp,
                                         int c0, bool colSafe,
                                         float4& a, float4& b, float4& c) {
    if (colSafe) {
        a = *(const float4*)(rowp + c0 - 4);
        b = *(const float4*)(rowp + c0);
        c = *(const float4*)(rowp + c0 + 4);
    } else {
        float w[12];
        #pragma unroll
        for (int i = 0; i < 12; ++i)
            w[i] = rowp[reflect_idx(c0 - 4 + i, IMG)];
        a = make_float4(w[0], w[1], w[2], w[3]);
        b = make_float4(w[4], w[5], w[6], w[7]);
        c = make_float4(w[8], w[9], w[10], w[11]);
    }
}

__global__ __launch_bounds__(THREADS, 8)
void locvar5_kernel(const float* __restrict__ in, float* __restrict__ out) {
    const int plane = blockIdx.z;
    const float* __restrict__ src = in + (size_t)plane * IMG * IMG;
    float* __restrict__ dst = out + (size_t)plane * IMG * IMG;

    const int tx = threadIdx.x & 15;
    const int ty = threadIdx.x >> 4;

    const int c0 = blockIdx.x * 64 + tx * 4;                  // first output col
    const int r0 = blockIdx.y * (16 * ROWS_PER_THREAD) + ty * ROWS_PER_THREAD;

    const bool colSafe = (c0 >= 4) && (c0 <= IMG - 8);
    const bool rowSafe = (r0 >= 2) && (r0 + ROWS_PER_THREAD + 2 <= IMG);

    float h[5][4], h2[5][4];

    // ---- Prime the ring with rows r0-2 .. r0+1 ----
    #pragma unroll
    for (int j = 0; j < 4; ++j) {
        const int gr = rowSafe ? (r0 - 2 + j) : reflect_idx(r0 - 2 + j, IMG);
        float4 a, b, c;
        load_row(src + (size_t)gr * IMG, c0, colSafe, a, b, c);
        rowsum(a, b, c, h[j], h2[j]);
    }

    float4* op = (float4*)(dst + (size_t)r0 * IMG + c0);
    const float inv_n = 1.0f / 25.0f;

    #pragma unroll
    for (int j = 4; j < 4 + ROWS_PER_THREAD; ++j) {
        const int gr = rowSafe ? (r0 - 2 + j) : reflect_idx(r0 - 2 + j, IMG);
        float4 a, b, c;
        load_row(src + (size_t)gr * IMG, c0, colSafe, a, b, c);
        rowsum(a, b, c, h[j % 5], h2[j % 5]);

        float4 o;
        float* po = (float*)&o;
        #pragma unroll
        for (int cc = 0; cc < 4; ++cc) {
            const float S = h[0][cc] + h[1][cc] + h[2][cc] + h[3][cc] + h[4][cc];
            const float T = h2[0][cc] + h2[1][cc] + h2[2][cc] + h2[3][cc] + h2[4][cc];
            const float m = S * inv_n;
            po[cc] = fmaf(-m, m, T * inv_n);
        }
        *op = o;
        op += IMG / 4;
    }
}

extern "C" void kernel_launch(void* const* d_in, const int* in_sizes, int n_in,
                              void* d_out, int out_size) {
    const float* in = (const float*)d_in[0];
    float* out = (float*)d_out;
    dim3 grid(IMG / 64, IMG / (16 * ROWS_PER_THREAD), NPLANES);
    locvar5_kernel<<<grid, THREADS>>>(in, out);
}

// round 7
// speedup vs baseline: 1.3542x; 1.3542x over previous
#include <cuda_runtime.h>

// Local 5x5 variance, reflect padding. float32 [16,3,1024,1024] -> same.
//
// Double-buffered cp.async pipeline:
//   CTA owns a 64-wide column strip, 512 rows = 8 stages of 64 rows.
//   Per stage: 68x72 float halo tile in smem (19.6KB), 2 buffers.
//   While computing stage s from buf[s&1], stage s+1 streams into buf[(s+1)&1]
//   via cp.async.cg -> DRAM stays busy across the compute phases.
//   Compute: per-thread 4 cols x 4 rows register ring (same as R4 math).

#define IMG 1024
#define NPLANES 48
#define TW 64
#define STAGE_H 64
#define STAGES 8            // 8 * 64 = 512 rows per CTA
#define SROWS 68            // STAGE_H + 4 halo
#define SC4 18              // 18 float4 = 72 floats per smem row
#define THREADS 256

__device__ __forceinline__ int reflect_idx(int i, int n) {
    if (i < 0) i = -i;
    if (i >= n) i = 2 * (n - 1) - i;
    return i;
}

__device__ __forceinline__ void cp_async16(void* smem_dst, const void* gsrc) {
    unsigned sa = (unsigned)__cvta_generic_to_shared(smem_dst);
    asm volatile("cp.async.cg.shared.global [%0], [%1], 16;\n" :: "r"(sa), "l"(gsrc));
}

// Horizontal 5-sums of x and x^2 for 4 output columns (floats 2..9 of a|b|c).
__device__ __forceinline__ void rowsum(float4 a, float4 b, float4 c,
                                       float* __restrict__ hh,
                                       float* __restrict__ hh2) {
    float x0 = a.z, x1 = a.w, x2 = b.x, x3 = b.y;
    float x4 = b.z, x5 = b.w, x6 = c.x, x7 = c.y;

    float h0 = x0 + x1 + x2 + x3 + x4;
    hh[0] = h0;
    hh[1] = h0    - x0 + x5;
    hh[2] = hh[1] - x1 + x6;
    hh[3] = hh[2] - x2 + x7;

    float q0 = x0 * x0, q1 = x1 * x1, q2 = x2 * x2, q3 = x3 * x3;
    float q4 = x4 * x4, q5 = x5 * x5, q6 = x6 * x6, q7 = x7 * x7;
    float g0 = q0 + q1 + q2 + q3 + q4;
    hh2[0] = g0;
    hh2[1] = g0     - q0 + q5;
    hh2[2] = hh2[1] - q1 + q6;
    hh2[3] = hh2[2] - q2 + q7;
}

__global__ __launch_bounds__(THREADS)
void locvar5_kernel(const float* __restrict__ in, float* __restrict__ out) {
    __shared__ float4 sbuf[2][SROWS * SC4];

    const int plane = blockIdx.z;
    const float* __restrict__ src = in + (size_t)plane * IMG * IMG;
    float* __restrict__ dst = out + (size_t)plane * IMG * IMG;

    const int bx = blockIdx.x * TW;
    const int byBase = blockIdx.y * (STAGES * STAGE_H);
    const int tid = threadIdx.x;
    const bool colEdge = (bx == 0) || (bx + TW == IMG);

    const int tx4 = tid & 15;
    const int ty  = tid >> 4;          // 16 strips of 4 rows

    // ---- stage loader: issue async copies (and scalar edge patches) ----
    auto load_stage = [&](int s, int buf) {
        const int r0 = byBase + s * STAGE_H - 2;
        #pragma unroll
        for (int i = tid; i < SROWS * SC4; i += THREADS) {
            const int row = i / SC4;
            const int c4  = i - row * SC4;
            const int gy  = reflect_idx(r0 + row, IMG);
            const int gx  = bx - 4 + c4 * 4;
            const float* gp = src + (size_t)gy * IMG + gx;
            if (!colEdge || (c4 >= 1 && c4 <= 16)) {
                cp_async16(&sbuf[buf][i], gp);
            } else {
                float4 v;
                v.x = src[(size_t)gy * IMG + reflect_idx(gx + 0, IMG)];
                v.y = src[(size_t)gy * IMG + reflect_idx(gx + 1, IMG)];
                v.z = src[(size_t)gy * IMG + reflect_idx(gx + 2, IMG)];
                v.w = src[(size_t)gy * IMG + reflect_idx(gx + 3, IMG)];
                sbuf[buf][i] = v;
            }
        }
        asm volatile("cp.async.commit_group;\n" ::: "memory");
    };

    // ---- prologue: load stage 0, wait ----
    load_stage(0, 0);
    asm volatile("cp.async.wait_group 0;\n" ::: "memory");
    __syncthreads();

    const float inv_n = 1.0f / 25.0f;

    for (int s = 0; s < STAGES; ++s) {
        if (s + 1 < STAGES) load_stage(s + 1, (s + 1) & 1);

        // ---- compute stage s from sbuf[s&1] ----
        const float4* sp = &sbuf[s & 1][(ty * 4) * SC4 + tx4];

        float h[5][4], h2[5][4];
        #pragma unroll
        for (int j = 0; j < 4; ++j)
            rowsum(sp[j * SC4], sp[j * SC4 + 1], sp[j * SC4 + 2], h[j], h2[j]);

        float4* op = (float4*)(dst + (size_t)(byBase + s * STAGE_H + ty * 4) * IMG
                                   + bx + tx4 * 4);
        #pragma unroll
        for (int j = 4; j < 8; ++j) {
            rowsum(sp[j * SC4], sp[j * SC4 + 1], sp[j * SC4 + 2],
                   h[j % 5], h2[j % 5]);
            float4 o;
            float* po = (float*)&o;
            #pragma unroll
            for (int cc = 0; cc < 4; ++cc) {
                const float S = h[0][cc] + h[1][cc] + h[2][cc] + h[3][cc] + h[4][cc];
                const float T = h2[0][cc] + h2[1][cc] + h2[2][cc] + h2[3][cc] + h2[4][cc];
                const float m = S * inv_n;
                po[cc] = fmaf(-m, m, T * inv_n);
            }
            *op = o;
            op += IMG / 4;
        }

        asm volatile("cp.async.wait_group 0;\n" ::: "memory");
        __syncthreads();
    }
}

extern "C" void kernel_launch(void* const* d_in, const int* in_sizes, int n_in,
                              void* d_out, int out_size) {
    const float* in = (const float*)d_in[0];
    float* out = (float*)d_out;
    dim3 grid(IMG / TW, IMG / (STAGES * STAGE_H), NPLANES);
    locvar5_kernel<<<grid, THREADS>>>(in, out);
}

// round 8
// speedup vs baseline: 1.5095x; 1.1147x over previous
#include <cuda_runtime.h>

// Local 5x5 variance, reflect padding. float32 [16,3,1024,1024] -> same.
//
// Double-buffered cp.async pipeline (same as R7) with register budget for
// 3 CTAs/SM: __launch_bounds__(256, 3) caps regs at ~85 so occupancy rises
// from 2 -> 3 CTAs/SM, increasing warps and in-flight async bytes per SM.

#define IMG 1024
#define NPLANES 48
#define TW 64
#define STAGE_H 64
#define STAGES 8            // 8 * 64 = 512 rows per CTA
#define SROWS 68            // STAGE_H + 4 halo
#define SC4 18              // 18 float4 = 72 floats per smem row
#define THREADS 256

__device__ __forceinline__ int reflect_idx(int i, int n) {
    if (i < 0) i = -i;
    if (i >= n) i = 2 * (n - 1) - i;
    return i;
}

__device__ __forceinline__ void cp_async16(void* smem_dst, const void* gsrc) {
    unsigned sa = (unsigned)__cvta_generic_to_shared(smem_dst);
    asm volatile("cp.async.cg.shared.global [%0], [%1], 16;\n" :: "r"(sa), "l"(gsrc));
}

// Horizontal 5-sums of x and x^2 for 4 output columns (floats 2..9 of a|b|c).
__device__ __forceinline__ void rowsum(float4 a, float4 b, float4 c,
                                       float* __restrict__ hh,
                                       float* __restrict__ hh2) {
    float x0 = a.z, x1 = a.w, x2 = b.x, x3 = b.y;
    float x4 = b.z, x5 = b.w, x6 = c.x, x7 = c.y;

    float h0 = x0 + x1 + x2 + x3 + x4;
    hh[0] = h0;
    hh[1] = h0    - x0 + x5;
    hh[2] = hh[1] - x1 + x6;
    hh[3] = hh[2] - x2 + x7;

    float q0 = x0 * x0, q1 = x1 * x1, q2 = x2 * x2, q3 = x3 * x3;
    float q4 = x4 * x4, q5 = x5 * x5, q6 = x6 * x6, q7 = x7 * x7;
    float g0 = q0 + q1 + q2 + q3 + q4;
    hh2[0] = g0;
    hh2[1] = g0     - q0 + q5;
    hh2[2] = hh2[1] - q1 + q6;
    hh2[3] = hh2[2] - q2 + q7;
}

__global__ __launch_bounds__(THREADS, 3)
void locvar5_kernel(const float* __restrict__ in, float* __restrict__ out) {
    __shared__ float4 sbuf[2][SROWS * SC4];

    const int plane = blockIdx.z;
    const float* __restrict__ src = in + (size_t)plane * IMG * IMG;
    float* __restrict__ dst = out + (size_t)plane * IMG * IMG;

    const int bx = blockIdx.x * TW;
    const int byBase = blockIdx.y * (STAGES * STAGE_H);
    const int tid = threadIdx.x;
    const bool colEdge = (bx == 0) || (bx + TW == IMG);

    const int tx4 = tid & 15;
    const int ty  = tid >> 4;          // 16 strips of 4 rows

    // ---- stage loader: issue async copies (and scalar edge patches) ----
    auto load_stage = [&](int s, int buf) {
        const int r0 = byBase + s * STAGE_H - 2;
        for (int i = tid; i < SROWS * SC4; i += THREADS) {
            const int row = i / SC4;
            const int c4  = i - row * SC4;
            const int gy  = reflect_idx(r0 + row, IMG);
            const int gx  = bx - 4 + c4 * 4;
            const float* gp = src + (size_t)gy * IMG + gx;
            if (!colEdge || (c4 >= 1 && c4 <= 16)) {
                cp_async16(&sbuf[buf][i], gp);
            } else {
                float4 v;
                v.x = src[(size_t)gy * IMG + reflect_idx(gx + 0, IMG)];
                v.y = src[(size_t)gy * IMG + reflect_idx(gx + 1, IMG)];
                v.z = src[(size_t)gy * IMG + reflect_idx(gx + 2, IMG)];
                v.w = src[(size_t)gy * IMG + reflect_idx(gx + 3, IMG)];
                sbuf[buf][i] = v;
            }
        }
        asm volatile("cp.async.commit_group;\n" ::: "memory");
    };

    // ---- prologue: load stage 0, wait ----
    load_stage(0, 0);
    asm volatile("cp.async.wait_group 0;\n" ::: "memory");
    __syncthreads();

    const float inv_n = 1.0f / 25.0f;

    for (int s = 0; s < STAGES; ++s) {
        if (s + 1 < STAGES) load_stage(s + 1, (s + 1) & 1);

        // ---- compute stage s from sbuf[s&1] ----
        const float4* sp = &sbuf[s & 1][(ty * 4) * SC4 + tx4];

        float h[5][4], h2[5][4];
        #pragma unroll
        for (int j = 0; j < 4; ++j)
            rowsum(sp[j * SC4], sp[j * SC4 + 1], sp[j * SC4 + 2], h[j], h2[j]);

        float4* op = (float4*)(dst + (size_t)(byBase + s * STAGE_H + ty * 4) * IMG
                                   + bx + tx4 * 4);
        #pragma unroll
        for (int j = 4; j < 8; ++j) {
            rowsum(sp[j * SC4], sp[j * SC4 + 1], sp[j * SC4 + 2],
                   h[j % 5], h2[j % 5]);
            float4 o;
            float* po = (float*)&o;
            #pragma unroll
            for (int cc = 0; cc < 4; ++cc) {
                const float S = h[0][cc] + h[1][cc] + h[2][cc] + h[3][cc] + h[4][cc];
                const float T = h2[0][cc] + h2[1][cc] + h2[2][cc] + h2[3][cc] + h2[4][cc];
                const float m = S * inv_n;
                po[cc] = fmaf(-m, m, T * inv_n);
            }
            *op = o;
            op += IMG / 4;
        }

        asm volatile("cp.async.wait_group 0;\n" ::: "memory");
        __syncthreads();
    }
}

extern "C" void kernel_launch(void* const* d_in, const int* in_sizes, int n_in,
                              void* d_out, int out_size) {
    const float* in = (const float*)d_in[0];
    float* out = (float*)d_out;
    dim3 grid(IMG / TW, IMG / (STAGES * STAGE_H), NPLANES);
    locvar5_kernel<<<grid, THREADS>>>(in, out);
}

// round 9
// speedup vs baseline: 1.5798x; 1.0465x over previous
#include <cuda_runtime.h>

// Local 5x5 variance, reflect padding. float32 [16,3,1024,1024] -> same.
//
// Double-buffered cp.async pipeline, 128-row stages:
//   CTA owns a 64-wide column strip, 512 rows = 4 stages of 128 rows.
//   Per stage: 132x72 float halo tile in dynamic smem (37.1KB), 2 buffers.
//   Thread owns 4 cols x 8 rows: 12 rowsums per 8 outputs (1.5x halo cost
//   vs 2x at 4-row strips). Loader uses incremental row/c4 indexing (no
//   div/mod) and skips reflect on interior stages.

#define IMG 1024
#define NPLANES 48
#define TW 64
#define STAGE_H 128
#define STAGES 4            // 4 * 128 = 512 rows per CTA
#define SROWS 132           // STAGE_H + 4 halo
#define SC4 18              // 18 float4 = 72 floats per smem row
#define SBUF_ELEMS (SROWS * SC4)          // 2376 float4 per buffer
#define SMEM_BYTES (2 * SBUF_ELEMS * 16)  // 76032 bytes
#define THREADS 256

__device__ __forceinline__ int reflect_idx(int i, int n) {
    if (i < 0) i = -i;
    if (i >= n) i = 2 * (n - 1) - i;
    return i;
}

__device__ __forceinline__ void cp_async16(void* smem_dst, const void* gsrc) {
    unsigned sa = (unsigned)__cvta_generic_to_shared(smem_dst);
    asm volatile("cp.async.cg.shared.global [%0], [%1], 16;\n" :: "r"(sa), "l"(gsrc));
}

// Horizontal 5-sums of x and x^2 for 4 output columns (floats 2..9 of a|b|c).
__device__ __forceinline__ void rowsum(float4 a, float4 b, float4 c,
                                       float* __restrict__ hh,
                                       float* __restrict__ hh2) {
    float x0 = a.z, x1 = a.w, x2 = b.x, x3 = b.y;
    float x4 = b.z, x5 = b.w, x6 = c.x, x7 = c.y;

    float h0 = x0 + x1 + x2 + x3 + x4;
    hh[0] = h0;
    hh[1] = h0    - x0 + x5;
    hh[2] = hh[1] - x1 + x6;
    hh[3] = hh[2] - x2 + x7;

    float q0 = x0 * x0, q1 = x1 * x1, q2 = x2 * x2, q3 = x3 * x3;
    float q4 = x4 * x4, q5 = x5 * x5, q6 = x6 * x6, q7 = x7 * x7;
    float g0 = q0 + q1 + q2 + q3 + q4;
    hh2[0] = g0;
    hh2[1] = g0     - q0 + q5;
    hh2[2] = hh2[1] - q1 + q6;
    hh2[3] = hh2[2] - q2 + q7;
}

__global__ __launch_bounds__(THREADS, 3)
void locvar5_kernel(const float* __restrict__ in, float* __restrict__ out) {
    extern __shared__ float4 sbuf[];   // 2 buffers of SBUF_ELEMS

    const int plane = blockIdx.z;
    const float* __restrict__ src = in + (size_t)plane * IMG * IMG;
    float* __restrict__ dst = out + (size_t)plane * IMG * IMG;

    const int bx = blockIdx.x * TW;
    const int byBase = blockIdx.y * (STAGES * STAGE_H);
    const int tid = threadIdx.x;
    const bool colEdge = (bx == 0) || (bx + TW == IMG);

    const int tx4 = tid & 15;
    const int ty  = tid >> 4;          // 16 strips of 8 rows

    const int rowInit = tid / SC4;     // one div/mod total, per stage reuse
    const int c4Init  = tid - rowInit * SC4;

    // ---- stage loader: async copies with incremental indexing ----
    auto load_stage = [&](int s, int buf) {
        float4* sb = sbuf + buf * SBUF_ELEMS;
        const int r0 = byBase + s * STAGE_H - 2;
        const bool rowsInterior = (r0 >= 0) && (r0 + SROWS <= IMG);
        int row = rowInit;
        int c4  = c4Init;
        while (row < SROWS) {
            const int gy = rowsInterior ? (r0 + row) : reflect_idx(r0 + row, IMG);
            const int gx = bx - 4 + c4 * 4;
            float4* sdst = sb + row * SC4 + c4;
            if (!colEdge || (c4 >= 1 && c4 <= 16)) {
                cp_async16(sdst, src + (size_t)gy * IMG + gx);
            } else {
                float4 v;
                v.x = src[(size_t)gy * IMG + reflect_idx(gx + 0, IMG)];
                v.y = src[(size_t)gy * IMG + reflect_idx(gx + 1, IMG)];
                v.z = src[(size_t)gy * IMG + reflect_idx(gx + 2, IMG)];
                v.w = src[(size_t)gy * IMG + reflect_idx(gx + 3, IMG)];
                *sdst = v;
            }
            // advance by 256 items: 256 = 14*18 + 4
            c4 += 4; row += 14;
            if (c4 >= SC4) { c4 -= SC4; ++row; }
        }
        asm volatile("cp.async.commit_group;\n" ::: "memory");
    };

    // ---- prologue: load stage 0, wait ----
    load_stage(0, 0);
    asm volatile("cp.async.wait_group 0;\n" ::: "memory");
    __syncthreads();

    const float inv_n = 1.0f / 25.0f;

    for (int s = 0; s < STAGES; ++s) {
        if (s + 1 < STAGES) load_stage(s + 1, (s + 1) & 1);

        // ---- compute stage s: 8 output rows per thread ----
        const float4* sp = sbuf + (s & 1) * SBUF_ELEMS + (ty * 8) * SC4 + tx4;

        float h[5][4], h2[5][4];
        #pragma unroll
        for (int j = 0; j < 4; ++j)
            rowsum(sp[j * SC4], sp[j * SC4 + 1], sp[j * SC4 + 2], h[j], h2[j]);

        float4* op = (float4*)(dst + (size_t)(byBase + s * STAGE_H + ty * 8) * IMG
                                   + bx + tx4 * 4);
        #pragma unroll
        for (int j = 4; j < 12; ++j) {
            rowsum(sp[j * SC4], sp[j * SC4 + 1], sp[j * SC4 + 2],
                   h[j % 5], h2[j % 5]);
            float4 o;
            float* po = (float*)&o;
            #pragma unroll
            for (int cc = 0; cc < 4; ++cc) {
                const float S = h[0][cc] + h[1][cc] + h[2][cc] + h[3][cc] + h[4][cc];
                const float T = h2[0][cc] + h2[1][cc] + h2[2][cc] + h2[3][cc] + h2[4][cc];
                const float m = S * inv_n;
                po[cc] = fmaf(-m, m, T * inv_n);
            }
            *op = o;
            op += IMG / 4;
        }

        asm volatile("cp.async.wait_group 0;\n" ::: "memory");
        __syncthreads();
    }
}

extern "C" void kernel_launch(void* const* d_in, const int* in_sizes, int n_in,
                              void* d_out, int out_size) {
    const float* in = (const float*)d_in[0];
    float* out = (float*)d_out;
    cudaFuncSetAttribute(locvar5_kernel,
                         cudaFuncAttributeMaxDynamicSharedMemorySize, SMEM_BYTES);
    dim3 grid(IMG / TW, IMG / (STAGES * STAGE_H), NPLANES);
    locvar5_kernel<<<grid, THREADS, SMEM_BYTES>>>(in, out);
}

// round 10
// speedup vs baseline: 1.7529x; 1.1096x over previous
#include <cuda_runtime.h>

// Local 5x5 variance, reflect padding. float32 [16,3,1024,1024] -> same.
//
// Double-buffered cp.async pipeline, 128-row stages, 256-row CTA strips:
//   grid = 3072 CTAs -> 6.9 waves of 444 (3 CTAs/SM x 148): <1% tail waste
//   (R9's 1536 CTAs = 3.46 waves wasted ~15% in the last wave).
//   Per stage: 132x72 float halo tile in dynamic smem (37.1KB), 2 buffers.
//   Thread owns 4 cols x 8 rows; incremental loader indexing; reflect
//   handling hoisted off the interior fast path.

#define IMG 1024
#define NPLANES 48
#define TW 64
#define STAGE_H 128
#define STAGES 2            // 2 * 128 = 256 rows per CTA
#define SROWS 132           // STAGE_H + 4 halo
#define SC4 18              // 18 float4 = 72 floats per smem row
#define SBUF_ELEMS (SROWS * SC4)          // 2376 float4 per buffer
#define SMEM_BYTES (2 * SBUF_ELEMS * 16)  // 76032 bytes
#define THREADS 256

__device__ __forceinline__ int reflect_idx(int i, int n) {
    if (i < 0) i = -i;
    if (i >= n) i = 2 * (n - 1) - i;
    return i;
}

__device__ __forceinline__ void cp_async16(void* smem_dst, const void* gsrc) {
    unsigned sa = (unsigned)__cvta_generic_to_shared(smem_dst);
    asm volatile("cp.async.cg.shared.global [%0], [%1], 16;\n" :: "r"(sa), "l"(gsrc));
}

// Horizontal 5-sums of x and x^2 for 4 output columns (floats 2..9 of a|b|c).
__device__ __forceinline__ void rowsum(float4 a, float4 b, float4 c,
                                       float* __restrict__ hh,
                                       float* __restrict__ hh2) {
    float x0 = a.z, x1 = a.w, x2 = b.x, x3 = b.y;
    float x4 = b.z, x5 = b.w, x6 = c.x, x7 = c.y;

    float h0 = x0 + x1 + x2 + x3 + x4;
    hh[0] = h0;
    hh[1] = h0    - x0 + x5;
    hh[2] = hh[1] - x1 + x6;
    hh[3] = hh[2] - x2 + x7;

    float q0 = x0 * x0, q1 = x1 * x1, q2 = x2 * x2, q3 = x3 * x3;
    float q4 = x4 * x4, q5 = x5 * x5, q6 = x6 * x6, q7 = x7 * x7;
    float g0 = q0 + q1 + q2 + q3 + q4;
    hh2[0] = g0;
    hh2[1] = g0     - q0 + q5;
    hh2[2] = hh2[1] - q1 + q6;
    hh2[3] = hh2[2] - q2 + q7;
}

__global__ __launch_bounds__(THREADS, 3)
void locvar5_kernel(const float* __restrict__ in, float* __restrict__ out) {
    extern __shared__ float4 sbuf[];   // 2 buffers of SBUF_ELEMS

    const int plane = blockIdx.z;
    const float* __restrict__ src = in + (size_t)plane * IMG * IMG;
    float* __restrict__ dst = out + (size_t)plane * IMG * IMG;

    const int bx = blockIdx.x * TW;
    const int byBase = blockIdx.y * (STAGES * STAGE_H);
    const int tid = threadIdx.x;
    const bool colEdge = (bx == 0) || (bx + TW == IMG);

    const int tx4 = tid & 15;
    const int ty  = tid >> 4;          // 16 strips of 8 rows

    const int rowInit = tid / SC4;     // one div/mod total, reused per stage
    const int c4Init  = tid - rowInit * SC4;

    // ---- stage loader: async copies with incremental indexing ----
    auto load_stage = [&](int s, int buf) {
        float4* sb = sbuf + buf * SBUF_ELEMS;
        const int r0 = byBase + s * STAGE_H - 2;
        const bool rowsInterior = (r0 >= 0) && (r0 + SROWS <= IMG);
        int row = rowInit;
        int c4  = c4Init;
        while (row < SROWS) {
            const int gy = rowsInterior ? (r0 + row) : reflect_idx(r0 + row, IMG);
            const int gx = bx - 4 + c4 * 4;
            float4* sdst = sb + row * SC4 + c4;
            if (!colEdge || (c4 >= 1 && c4 <= 16)) {
                cp_async16(sdst, src + (size_t)gy * IMG + gx);
            } else {
                float4 v;
                v.x = src[(size_t)gy * IMG + reflect_idx(gx + 0, IMG)];
                v.y = src[(size_t)gy * IMG + reflect_idx(gx + 1, IMG)];
                v.z = src[(size_t)gy * IMG + reflect_idx(gx + 2, IMG)];
                v.w = src[(size_t)gy * IMG + reflect_idx(gx + 3, IMG)];
                *sdst = v;
            }
            // advance by 256 items: 256 = 14*18 + 4
            c4 += 4; row += 14;
            if (c4 >= SC4) { c4 -= SC4; ++row; }
        }
        asm volatile("cp.async.commit_group;\n" ::: "memory");
    };

    // ---- prologue: load stage 0, wait ----
    load_stage(0, 0);
    asm volatile("cp.async.wait_group 0;\n" ::: "memory");
    __syncthreads();

    const float inv_n = 1.0f / 25.0f;

    #pragma unroll
    for (int s = 0; s < STAGES; ++s) {
        if (s + 1 < STAGES) load_stage(s + 1, (s + 1) & 1);

        // ---- compute stage s: 8 output rows per thread ----
        const float4* sp = sbuf + (s & 1) * SBUF_ELEMS + (ty * 8) * SC4 + tx4;

        float h[5][4], h2[5][4];
        #pragma unroll
        for (int j = 0; j < 4; ++j)
            rowsum(sp[j * SC4], sp[j * SC4 + 1], sp[j * SC4 + 2], h[j], h2[j]);

        float4* op = (float4*)(dst + (size_t)(byBase + s * STAGE_H + ty * 8) * IMG
                                   + bx + tx4 * 4);
        #pragma unroll
        for (int j = 4; j < 12; ++j) {
            rowsum(sp[j * SC4], sp[j * SC4 + 1], sp[j * SC4 + 2],
                   h[j % 5], h2[j % 5]);
            float4 o;
            float* po = (float*)&o;
            #pragma unroll
            for (int cc = 0; cc < 4; ++cc) {
                const float S = h[0][cc] + h[1][cc] + h[2][cc] + h[3][cc] + h[4][cc];
                const float T = h2[0][cc] + h2[1][cc] + h2[2][cc] + h2[3][cc] + h2[4][cc];
                const float m = S * inv_n;
                po[cc] = fmaf(-m, m, T * inv_n);
            }
            *op = o;
            op += IMG / 4;
        }

        if (s + 1 < STAGES) {
            asm volatile("cp.async.wait_group 0;\n" ::: "memory");
            __syncthreads();
        }
    }
}

extern "C" void kernel_launch(void* const* d_in, const int* in_sizes, int n_in,
                              void* d_out, int out_size) {
    const float* in = (const float*)d_in[0];
    float* out = (float*)d_out;
    cudaFuncSetAttribute(locvar5_kernel,
                         cudaFuncAttributeMaxDynamicSharedMemorySize, SMEM_BYTES);
    dim3 grid(IMG / TW, IMG / (STAGES * STAGE_H), NPLANES);
    locvar5_kernel<<<grid, THREADS, SMEM_BYTES>>>(in, out);
}